// round 3
// baseline (speedup 1.0000x reference)
#include <cuda_runtime.h>
#include <math.h>
#include <stdint.h>

#define NB 4096

// Scratch (device globals -- no allocation allowed)
__device__ float g_coef[NB * 8];
__device__ float g_h0[NB * 1024];
__device__ float g_h1[NB * 1024];
// tf32-packed, fragment-paired weights: [K/32][16][N] x uint2 {tf32(k), tf32(k+4)}
__device__ uint32_t g_wp0[(4608 / 2) * 1024 * 2];
__device__ uint32_t g_wp1[(8704 / 2) * 1024 * 2];
__device__ uint32_t g_wp2[(8704 / 2) * 512 * 2];

__device__ __forceinline__ float elu1(float x) {
    return x > 0.f ? x : expm1f(x);
}

// Round-to-nearest fp32 -> tf32 (RNA: truncation would bias the dot product).
__device__ __forceinline__ uint32_t f2tf(float x) {
    uint32_t r;
    asm("cvt.rna.tf32.f32 %0, %1;" : "=r"(r) : "f"(x));
    return r;
}

__device__ __forceinline__ void cp16(uint32_t smem_addr, const void* gptr) {
    asm volatile("cp.async.cg.shared.global [%0], [%1], 16;\n"
                 :: "r"(smem_addr), "l"(gptr));
}
__device__ __forceinline__ void cp_commit() {
    asm volatile("cp.async.commit_group;\n" ::);
}
__device__ __forceinline__ void cp_wait0() {
    asm volatile("cp.async.wait_group 0;\n" ::);
}

__device__ __forceinline__ void mma_tf32(float& d0, float& d1, float& d2, float& d3,
                                         uint32_t a0, uint32_t a1, uint32_t a2, uint32_t a3,
                                         uint32_t b0, uint32_t b1) {
    asm volatile(
        "mma.sync.aligned.m16n8k8.row.col.f32.tf32.tf32.f32 "
        "{%0,%1,%2,%3}, {%4,%5,%6,%7}, {%8,%9}, {%0,%1,%2,%3};\n"
        : "+f"(d0), "+f"(d1), "+f"(d2), "+f"(d3)
        : "r"(a0), "r"(a1), "r"(a2), "r"(a3), "r"(b0), "r"(b1));
}

// ---------------------------------------------------------------------------
// Weight pack: W[k][n] (k = e*IN + i, row-major) -> Wp[(kt*16+kp)*N + n] as
// uint2 { tf32(W[k1][n]), tf32(W[k1+4][n]) }, k1 = kt*32 + (kp>>2)*8 + (kp&3).
// Reads 2 coalesced rows, writes coalesced uint2.
// ---------------------------------------------------------------------------
__global__ __launch_bounds__(256) void pack_kernel(
    const float* __restrict__ W, uint32_t* __restrict__ Wp, int N, int total)
{
    int idx = blockIdx.x * 256 + threadIdx.x;   // over (K/2)*N
    if (idx >= total) return;
    int n = idx % N;
    int r = idx / N;           // global pair-row = kt*16 + kp
    int kt = r >> 4, kp = r & 15;
    int k1 = kt * 32 + (kp >> 2) * 8 + (kp & 3);
    uint2 v;
    v.x = f2tf(W[(size_t)k1 * N + n]);
    v.y = f2tf(W[(size_t)(k1 + 4) * N + n]);
    ((uint2*)Wp)[(size_t)r * N + n] = v;
}

// ---------------------------------------------------------------------------
// Gate MLP: x0=[z|c] -> elu(576->128) -> elu(128->128) -> softmax(128->8)
// ---------------------------------------------------------------------------
__global__ __launch_bounds__(128) void gate_kernel(
    const float* __restrict__ z, const float* __restrict__ c,
    const float* __restrict__ gw1, const float* __restrict__ gb1,
    const float* __restrict__ gw2, const float* __restrict__ gb2,
    const float* __restrict__ gw3, const float* __restrict__ gb3,
    float* __restrict__ coef)
{
    constexpr int R = 8;
    __shared__ float xs[R][576];
    __shared__ float h1s[R][128];
    __shared__ float h2s[R][128];
    __shared__ float lg[R][8];

    const int tid = threadIdx.x;
    const int b0 = blockIdx.x * R;

    for (int idx = tid; idx < R * 576; idx += 128) {
        int r = idx / 576;
        int i = idx - r * 576;
        xs[r][i] = (i < 64) ? z[(b0 + r) * 64 + i] : c[(b0 + r) * 512 + (i - 64)];
    }
    __syncthreads();

    float acc[R];
    {
        float bv = gb1[tid];
#pragma unroll
        for (int r = 0; r < R; r++) acc[r] = bv;
        for (int i = 0; i < 576; i++) {
            float w = gw1[i * 128 + tid];
#pragma unroll
            for (int r = 0; r < R; r++) acc[r] = fmaf(xs[r][i], w, acc[r]);
        }
#pragma unroll
        for (int r = 0; r < R; r++) h1s[r][tid] = elu1(acc[r]);
    }
    __syncthreads();

    {
        float bv = gb2[tid];
#pragma unroll
        for (int r = 0; r < R; r++) acc[r] = bv;
        for (int i = 0; i < 128; i++) {
            float w = gw2[i * 128 + tid];
#pragma unroll
            for (int r = 0; r < R; r++) acc[r] = fmaf(h1s[r][i], w, acc[r]);
        }
#pragma unroll
        for (int r = 0; r < R; r++) h2s[r][tid] = elu1(acc[r]);
    }
    __syncthreads();

    if (tid < 64) {
        int r = tid >> 3, e = tid & 7;
        float s = gb3[e];
        for (int i = 0; i < 128; i++) s = fmaf(h2s[r][i], gw3[i * 8 + e], s);
        lg[r][e] = s;
    }
    __syncthreads();

    if (tid < 64) {
        int r = tid >> 3, e = tid & 7;
        float mx = lg[r][0];
#pragma unroll
        for (int j = 1; j < 8; j++) mx = fmaxf(mx, lg[r][j]);
        float sum = 0.f;
#pragma unroll
        for (int j = 0; j < 8; j++) sum += expf(lg[r][j] - mx);
        coef[(b0 + r) * 8 + e] = expf(lg[r][e] - mx) / sum;
    }
}

// ---------------------------------------------------------------------------
// Mixed layer dense tf32 GEMM, conversion-free mainloop.
// B: cp.async from pre-packed tf32 pair layout, fragment = 1x LDS.64.
// A: LDG->cvt+coef->STS in permuted layout, fragment pair = 1x LDS.64.
// Block 128 x BN, 8 warps (4m x 2n), mma m16n8k8, single sync per k-tile.
// ---------------------------------------------------------------------------
template <int XC, int N, int BN, bool ELU>
__global__ __launch_bounds__(256, 2) void mixed_tc_kernel(
    const float* __restrict__ z,
    const float* __restrict__ xp,
    const uint32_t* __restrict__ Wp,
    const float* __restrict__ bias,
    const float* __restrict__ coef,
    float* __restrict__ out)
{
    constexpr int BM = 128;
    constexpr int BK = 32;
    constexpr int IN = 64 + XC;
    constexpr int K = 8 * IN;
    constexpr int NT = K / BK;
    constexpr int AST = 36;         // A row stride (u32)
    constexpr int BNp = BN + 8;     // B pair-row stride (uint2); (BN+8)%16==8 -> bank-spread
    constexpr int WN = BN / 2;
    constexpr int NTN = WN / 8;

    extern __shared__ char smraw[];
    uint32_t* As = (uint32_t*)smraw;            // 2 * BM * AST
    uint32_t* Bp = As + 2 * BM * AST;           // 2 * 16 * BNp * 2
    float* coefS = (float*)(Bp + 2 * 16 * BNp * 2);  // BM * 9
    float* biasS = coefS + BM * 9;                   // 8 * BN

    const int tid = threadIdx.x;
    const int m0 = blockIdx.y * BM;
    const int n0 = blockIdx.x * BN;
    const int w = tid >> 5, lane = tid & 31;
    const int wm0 = (w & 3) * 32;
    const int wn0 = (w >> 2) * WN;
    const int g8 = lane >> 2;
    const int t4 = lane & 3;

    // --- B staging: pure cp.async of pre-converted pairs ---
    constexpr int BCH = 8 * BN / 256;   // 16B chunks per thread (4 or 2)
    auto cpB = [&](int kt, int stg) {
        uint32_t dbase = (uint32_t)__cvta_generic_to_shared(Bp + stg * 16 * BNp * 2);
        const uint32_t* src = Wp + ((size_t)kt * 16 * N + n0) * 2;
#pragma unroll
        for (int j = 0; j < BCH; j++) {
            int idx = j * 256 + tid;
            int r = idx / (BN / 2);
            int c16 = idx - r * (BN / 2);
            cp16(dbase + (r * BNp * 2 + c16 * 4) * 4, src + (size_t)r * N * 2 + c16 * 4);
        }
    };

    // --- A staging: LDG (col fixed per thread, 4 rows) ---
    const int kc4 = (tid & 7) * 4;
    const int ar0 = tid >> 3;
    auto ldgA = [&](int kt, float4* ra) {
        const int e = (kt * BK) / IN;
        const int i0 = kt * BK - e * IN;
        const float* base;
        int stride;
        if (i0 < 64) { base = z + (size_t)m0 * 64 + i0 + kc4; stride = 64; }
        else         { base = xp + (size_t)m0 * XC + (i0 - 64) + kc4; stride = XC; }
#pragma unroll
        for (int j = 0; j < 4; j++)
            ra[j] = *(const float4*)(base + (size_t)(ar0 + 32 * j) * stride);
    };
    auto stsA = [&](int kt, int stg, const float4* ra) {
        const int e = (kt * BK) / IN;
        uint32_t* dst = As + stg * BM * AST;
#pragma unroll
        for (int j = 0; j < 4; j++) {
            const int row = ar0 + 32 * j;
            const float cf = coefS[row * 9 + e];
            const float v[4] = { ra[j].x, ra[j].y, ra[j].z, ra[j].w };
#pragma unroll
            for (int q = 0; q < 4; q++) {
                int k = kc4 + q;
                int cp = (k & 24) | (((k & 3) << 1) | ((k >> 2) & 1));
                dst[row * AST + cp] = f2tf(v[q] * cf);
            }
        }
    };

    // --- prologue ---
    cpB(0, 0);
    cp_commit();
    float4 ra[4];
    ldgA(0, ra);

    for (int idx = tid; idx < BM * 8; idx += 256)
        coefS[(idx >> 3) * 9 + (idx & 7)] = coef[(size_t)(m0 + (idx >> 3)) * 8 + (idx & 7)];
    for (int idx = tid; idx < 8 * BN; idx += 256) {
        int e = idx / BN, cn = idx - e * BN;
        biasS[e * BN + cn] = bias[(size_t)e * N + n0 + cn];
    }
    __syncthreads();           // coefS visible to stsA
    stsA(0, 0, ra);
    cp_wait0();
    __syncthreads();

    float acc[2][NTN][4];
#pragma unroll
    for (int mt = 0; mt < 2; mt++)
#pragma unroll
        for (int nt = 0; nt < NTN; nt++)
#pragma unroll
            for (int q = 0; q < 4; q++) acc[mt][nt][q] = 0.f;

    int buf = 0;
    for (int kt = 0; kt < NT; kt++) {
        const bool more = (kt + 1 < NT);
        if (more) {
            cpB(kt + 1, buf ^ 1);
            cp_commit();
            ldgA(kt + 1, ra);
        }

        const uint32_t* Ab = As + buf * BM * AST;
        const uint32_t* Bb = Bp + buf * 16 * BNp * 2;
#pragma unroll
        for (int s = 0; s < 4; s++) {
            uint32_t af[2][4];
#pragma unroll
            for (int mt = 0; mt < 2; mt++) {
                const int r0 = wm0 + mt * 16 + g8;
                uint2 p0 = *(const uint2*)&Ab[r0 * AST + s * 8 + t4 * 2];
                uint2 p1 = *(const uint2*)&Ab[(r0 + 8) * AST + s * 8 + t4 * 2];
                af[mt][0] = p0.x; af[mt][1] = p1.x; af[mt][2] = p0.y; af[mt][3] = p1.y;
            }
#pragma unroll
            for (int nt = 0; nt < NTN; nt++) {
                const int cn = wn0 + nt * 8 + g8;
                uint2 bp = *(const uint2*)&Bb[(s * 4 + t4) * BNp * 2 + cn * 2];
#pragma unroll
                for (int mt = 0; mt < 2; mt++)
                    mma_tf32(acc[mt][nt][0], acc[mt][nt][1], acc[mt][nt][2], acc[mt][nt][3],
                             af[mt][0], af[mt][1], af[mt][2], af[mt][3], bp.x, bp.y);
            }
        }

        if (more) {
            stsA(kt + 1, buf ^ 1, ra);
            cp_wait0();
        }
        __syncthreads();
        buf ^= 1;
    }

    // --- epilogue: + coef·bias, activation, store ---
#pragma unroll
    for (int mt = 0; mt < 2; mt++) {
#pragma unroll
        for (int half = 0; half < 2; half++) {
            const int rl = wm0 + mt * 16 + g8 + half * 8;
            float cfr[8];
#pragma unroll
            for (int e2 = 0; e2 < 8; e2++) cfr[e2] = coefS[rl * 9 + e2];
            float* orow = out + (size_t)(m0 + rl) * N + n0;
#pragma unroll
            for (int nt = 0; nt < NTN; nt++) {
                const int cl = wn0 + nt * 8 + t4 * 2;
                float v0 = acc[mt][nt][half * 2 + 0];
                float v1 = acc[mt][nt][half * 2 + 1];
#pragma unroll
                for (int e2 = 0; e2 < 8; e2++) {
                    v0 = fmaf(cfr[e2], biasS[e2 * BN + cl], v0);
                    v1 = fmaf(cfr[e2], biasS[e2 * BN + cl + 1], v1);
                }
                if (ELU) { v0 = elu1(v0); v1 = elu1(v1); }
                *(float2*)(orow + cl) = make_float2(v0, v1);
            }
        }
    }
}

// ---------------------------------------------------------------------------

static constexpr int smem_bytes(int BN) {
    return (2 * 128 * 36 + 2 * 16 * (BN + 8) * 2 + 128 * 9 + 8 * BN) * 4;
}

extern "C" void kernel_launch(void* const* d_in, const int* in_sizes, int n_in,
                              void* d_out, int out_size)
{
    const float* z   = (const float*)d_in[0];
    const float* c   = (const float*)d_in[1];
    const float* w0  = (const float*)d_in[2];
    const float* b0  = (const float*)d_in[3];
    const float* w1  = (const float*)d_in[4];
    const float* b1  = (const float*)d_in[5];
    const float* w2  = (const float*)d_in[6];
    const float* b2  = (const float*)d_in[7];
    const float* gw1 = (const float*)d_in[8];
    const float* gb1 = (const float*)d_in[9];
    const float* gw2 = (const float*)d_in[10];
    const float* gb2 = (const float*)d_in[11];
    const float* gw3 = (const float*)d_in[12];
    const float* gb3 = (const float*)d_in[13];

    float *coef, *h0, *h1;
    uint32_t *wp0, *wp1, *wp2;
    cudaGetSymbolAddress((void**)&coef, g_coef);
    cudaGetSymbolAddress((void**)&h0, g_h0);
    cudaGetSymbolAddress((void**)&h1, g_h1);
    cudaGetSymbolAddress((void**)&wp0, g_wp0);
    cudaGetSymbolAddress((void**)&wp1, g_wp1);
    cudaGetSymbolAddress((void**)&wp2, g_wp2);

    cudaFuncSetAttribute(mixed_tc_kernel<512, 1024, 128, true>,
                         cudaFuncAttributeMaxDynamicSharedMemorySize, smem_bytes(128));
    cudaFuncSetAttribute(mixed_tc_kernel<1024, 1024, 128, true>,
                         cudaFuncAttributeMaxDynamicSharedMemorySize, smem_bytes(128));
    cudaFuncSetAttribute(mixed_tc_kernel<1024, 512, 64, false>,
                         cudaFuncAttributeMaxDynamicSharedMemorySize, smem_bytes(64));

    // pack weights to tf32 pair layout
    {
        int t0 = (4608 / 2) * 1024;
        int t1 = (8704 / 2) * 1024;
        int t2 = (8704 / 2) * 512;
        pack_kernel<<<(t0 + 255) / 256, 256>>>(w0, wp0, 1024, t0);
        pack_kernel<<<(t1 + 255) / 256, 256>>>(w1, wp1, 1024, t1);
        pack_kernel<<<(t2 + 255) / 256, 256>>>(w2, wp2, 512, t2);
    }

    gate_kernel<<<NB / 8, 128>>>(z, c, gw1, gb1, gw2, gb2, gw3, gb3, coef);

    // layer0: M=4096, K=4608, N=1024
    mixed_tc_kernel<512, 1024, 128, true>
        <<<dim3(1024 / 128, NB / 128), 256, smem_bytes(128)>>>(z, c, wp0, b0, coef, h0);

    // layer1: M=4096, K=8704, N=1024
    mixed_tc_kernel<1024, 1024, 128, true>
        <<<dim3(1024 / 128, NB / 128), 256, smem_bytes(128)>>>(z, h0, wp1, b1, coef, h1);

    // layer2: M=4096, K=8704, N=512
    mixed_tc_kernel<1024, 512, 64, false>
        <<<dim3(512 / 64, NB / 128), 256, smem_bytes(64)>>>(z, h1, wp2, b2, coef, (float*)d_out);
}

// round 4
// speedup vs baseline: 1.0393x; 1.0393x over previous
#include <cuda_runtime.h>
#include <math.h>
#include <stdint.h>

#define NB 4096

// Scratch (device globals -- no allocation allowed)
__device__ float g_coef[NB * 8];
__device__ float g_h0[NB * 1024];
__device__ float g_h1[NB * 1024];
// tf32-packed, fragment-paired weights: [K/32][16][N] x uint2 {tf32(k), tf32(k+4)}
__device__ uint32_t g_wp0[(4608 / 2) * 1024 * 2];
__device__ uint32_t g_wp1[(8704 / 2) * 1024 * 2];
__device__ uint32_t g_wp2[(8704 / 2) * 512 * 2];

__device__ __forceinline__ float elu1(float x) {
    return x > 0.f ? x : expm1f(x);
}

__device__ __forceinline__ uint32_t f2tf(float x) {
    uint32_t r;
    asm("cvt.rna.tf32.f32 %0, %1;" : "=r"(r) : "f"(x));
    return r;
}

__device__ __forceinline__ void cp16(uint32_t smem_addr, const void* gptr) {
    asm volatile("cp.async.cg.shared.global [%0], [%1], 16;\n"
                 :: "r"(smem_addr), "l"(gptr));
}
__device__ __forceinline__ void cp_commit() {
    asm volatile("cp.async.commit_group;\n" ::);
}
__device__ __forceinline__ void cp_wait1() {
    asm volatile("cp.async.wait_group 1;\n" ::);
}
__device__ __forceinline__ void cp_wait0() {
    asm volatile("cp.async.wait_group 0;\n" ::);
}

__device__ __forceinline__ void mma_tf32(float& d0, float& d1, float& d2, float& d3,
                                         uint32_t a0, uint32_t a1, uint32_t a2, uint32_t a3,
                                         uint32_t b0, uint32_t b1) {
    asm volatile(
        "mma.sync.aligned.m16n8k8.row.col.f32.tf32.tf32.f32 "
        "{%0,%1,%2,%3}, {%4,%5,%6,%7}, {%8,%9}, {%0,%1,%2,%3};\n"
        : "+f"(d0), "+f"(d1), "+f"(d2), "+f"(d3)
        : "r"(a0), "r"(a1), "r"(a2), "r"(a3), "r"(b0), "r"(b1));
}

// ---------------------------------------------------------------------------
// Weight pack: W[k][n] -> Wp[(kt*16+kp)*N + n] as uint2 { tf32(W[k1][n]),
// tf32(W[k1+4][n]) }, k1 = kt*32 + (kp>>2)*8 + (kp&3).  (validated in R3)
// ---------------------------------------------------------------------------
__global__ __launch_bounds__(256) void pack_kernel(
    const float* __restrict__ W, uint32_t* __restrict__ Wp, int N, int total)
{
    int idx = blockIdx.x * 256 + threadIdx.x;
    if (idx >= total) return;
    int n = idx % N;
    int r = idx / N;
    int kt = r >> 4, kp = r & 15;
    int k1 = kt * 32 + (kp >> 2) * 8 + (kp & 3);
    uint2 v;
    v.x = f2tf(W[(size_t)k1 * N + n]);
    v.y = f2tf(W[(size_t)(k1 + 4) * N + n]);
    ((uint2*)Wp)[(size_t)r * N + n] = v;
}

// ---------------------------------------------------------------------------
// Gate MLP (unchanged)
// ---------------------------------------------------------------------------
__global__ __launch_bounds__(128) void gate_kernel(
    const float* __restrict__ z, const float* __restrict__ c,
    const float* __restrict__ gw1, const float* __restrict__ gb1,
    const float* __restrict__ gw2, const float* __restrict__ gb2,
    const float* __restrict__ gw3, const float* __restrict__ gb3,
    float* __restrict__ coef)
{
    constexpr int R = 8;
    __shared__ float xs[R][576];
    __shared__ float h1s[R][128];
    __shared__ float h2s[R][128];
    __shared__ float lg[R][8];

    const int tid = threadIdx.x;
    const int b0 = blockIdx.x * R;

    for (int idx = tid; idx < R * 576; idx += 128) {
        int r = idx / 576;
        int i = idx - r * 576;
        xs[r][i] = (i < 64) ? z[(b0 + r) * 64 + i] : c[(b0 + r) * 512 + (i - 64)];
    }
    __syncthreads();

    float acc[R];
    {
        float bv = gb1[tid];
#pragma unroll
        for (int r = 0; r < R; r++) acc[r] = bv;
#pragma unroll 4
        for (int i = 0; i < 576; i++) {
            float w = gw1[i * 128 + tid];
#pragma unroll
            for (int r = 0; r < R; r++) acc[r] = fmaf(xs[r][i], w, acc[r]);
        }
#pragma unroll
        for (int r = 0; r < R; r++) h1s[r][tid] = elu1(acc[r]);
    }
    __syncthreads();

    {
        float bv = gb2[tid];
#pragma unroll
        for (int r = 0; r < R; r++) acc[r] = bv;
#pragma unroll 4
        for (int i = 0; i < 128; i++) {
            float w = gw2[i * 128 + tid];
#pragma unroll
            for (int r = 0; r < R; r++) acc[r] = fmaf(h1s[r][i], w, acc[r]);
        }
#pragma unroll
        for (int r = 0; r < R; r++) h2s[r][tid] = elu1(acc[r]);
    }
    __syncthreads();

    if (tid < 64) {
        int r = tid >> 3, e = tid & 7;
        float s = gb3[e];
        for (int i = 0; i < 128; i++) s = fmaf(h2s[r][i], gw3[i * 8 + e], s);
        lg[r][e] = s;
    }
    __syncthreads();

    if (tid < 64) {
        int r = tid >> 3, e = tid & 7;
        float mx = lg[r][0];
#pragma unroll
        for (int j = 1; j < 8; j++) mx = fmaxf(mx, lg[r][j]);
        float sum = 0.f;
#pragma unroll
        for (int j = 0; j < 8; j++) sum += expf(lg[r][j] - mx);
        coef[(b0 + r) * 8 + e] = expf(lg[r][e] - mx) / sum;
    }
}

// ---------------------------------------------------------------------------
// Mixed layer dense tf32 GEMM, conversion-free mainloop, R2-style 2-stage
// pipeline (wait_group 1 => one full k-tile of cp.async slack).
//   B: cp.async of pre-packed tf32 pairs; fragment = 1 LDS.64 (BNp=BN+4, conflict-free)
//   A: LDG -> (cvt+coef) once at STS; fragment pair = 1 LDS.64 (AST=40, conflict-free)
// ---------------------------------------------------------------------------
template <int XC, int N, int BN, bool ELU>
__global__ __launch_bounds__(256, 2) void mixed_tc_kernel(
    const float* __restrict__ z,
    const float* __restrict__ xp,
    const uint32_t* __restrict__ Wp,
    const float* __restrict__ bias,
    const float* __restrict__ coef,
    float* __restrict__ out)
{
    constexpr int BM = 128;
    constexpr int BK = 32;
    constexpr int IN = 64 + XC;
    constexpr int K = 8 * IN;
    constexpr int NT = K / BK;
    constexpr int AST = 40;         // u32 row stride; AST/2 % 16 == 4 -> LDS.64 conflict-free
    constexpr int BNp = BN + 4;     // pair-row stride; BNp % 16 == 4  -> LDS.64 conflict-free
    constexpr int WN = BN / 2;
    constexpr int NTN = WN / 8;

    extern __shared__ char smraw[];
    uint32_t* As = (uint32_t*)smraw;                 // 2 * BM * AST
    uint32_t* Bp = As + 2 * BM * AST;                // 2 * 16 * BNp * 2
    float* coefS = (float*)(Bp + 2 * 16 * BNp * 2);  // BM * 9
    float* biasS = coefS + BM * 9;                   // 8 * BN

    const int tid = threadIdx.x;
    const int m0 = blockIdx.y * BM;
    const int n0 = blockIdx.x * BN;
    const int w = tid >> 5, lane = tid & 31;
    const int wm0 = (w & 3) * 32;
    const int wn0 = (w >> 2) * WN;
    const int g8 = lane >> 2;
    const int t4 = lane & 3;

    // --- B staging: pure cp.async of pre-converted pairs ---
    constexpr int BCH = BN / 32;    // 16B chunks per thread (4 or 2)
    auto cpB = [&](int kt, int stg) {
        uint32_t dbase = (uint32_t)__cvta_generic_to_shared(Bp + stg * 16 * BNp * 2);
        const uint32_t* src = Wp + (size_t)kt * 16 * N * 2 + n0 * 2;
#pragma unroll
        for (int j = 0; j < BCH; j++) {
            int idx = j * 256 + tid;
            int r = idx / (BN / 2);
            int c16 = idx - r * (BN / 2);
            cp16(dbase + (r * BNp * 2 + c16 * 4) * 4, src + (size_t)r * N * 2 + c16 * 4);
        }
    };

    // --- A staging: LDG 4 rows x float4, convert+scale at STS ---
    const int kc4 = (tid & 7) * 4;
    const int ar0 = tid >> 3;
    auto ldgA = [&](int kt, float4* ra) {
        const int e = (kt * BK) / IN;
        const int i0 = kt * BK - e * IN;
        const float* base;
        int stride;
        if (i0 < 64) { base = z + (size_t)m0 * 64 + i0 + kc4; stride = 64; }
        else         { base = xp + (size_t)m0 * XC + (i0 - 64) + kc4; stride = XC; }
#pragma unroll
        for (int j = 0; j < 4; j++)
            ra[j] = *(const float4*)(base + (size_t)(ar0 + 32 * j) * stride);
    };
    auto stsA = [&](int kt, int stg, const float4* ra) {
        const int e = (kt * BK) / IN;
        uint32_t* dst = As + stg * BM * AST;
#pragma unroll
        for (int j = 0; j < 4; j++) {
            const int row = ar0 + 32 * j;
            const float cf = coefS[row * 9 + e];
            const float v[4] = { ra[j].x, ra[j].y, ra[j].z, ra[j].w };
#pragma unroll
            for (int q = 0; q < 4; q++) {
                int k = kc4 + q;
                int cp = (k & 24) | (((k & 3) << 1) | ((k >> 2) & 1));
                dst[row * AST + cp] = f2tf(v[q] * cf);
            }
        }
    };

    // --- prologue: stage 0 in flight, coef/bias, A0 staged ---
    cpB(0, 0);
    cp_commit();
    float4 ra[4];
    ldgA(0, ra);

    for (int idx = tid; idx < BM * 8; idx += 256)
        coefS[(idx >> 3) * 9 + (idx & 7)] = coef[(size_t)(m0 + (idx >> 3)) * 8 + (idx & 7)];
    for (int idx = tid; idx < 8 * BN; idx += 256) {
        int e = idx / BN, cn = idx - e * BN;
        biasS[e * BN + cn] = bias[(size_t)e * N + n0 + cn];
    }
    __syncthreads();           // coefS visible for stsA
    stsA(0, 0, ra);

    float acc[2][NTN][4];
#pragma unroll
    for (int mt = 0; mt < 2; mt++)
#pragma unroll
        for (int nt = 0; nt < NTN; nt++)
#pragma unroll
            for (int q = 0; q < 4; q++) acc[mt][nt][q] = 0.f;

    int buf = 0;
    for (int kt = 0; kt < NT; kt++) {
        const bool more = (kt + 1 < NT);
        if (more) {
            cpB(kt + 1, buf ^ 1);   // into the buffer iter kt-1 just finished reading
            cp_commit();
            ldgA(kt + 1, ra);
            cp_wait1();             // stage kt complete; kt+1 still in flight
        } else {
            cp_wait0();
        }
        __syncthreads();            // Bs[buf] (+ As[buf] STS from prev iter) visible

        const uint32_t* Ab = As + buf * BM * AST;
        const uint32_t* Bb = Bp + buf * 16 * BNp * 2;
#pragma unroll
        for (int s = 0; s < 4; s++) {
            uint32_t af[2][4];
#pragma unroll
            for (int mt = 0; mt < 2; mt++) {
                const int r0 = wm0 + mt * 16 + g8;
                uint2 p0 = *(const uint2*)&Ab[r0 * AST + s * 8 + t4 * 2];
                uint2 p1 = *(const uint2*)&Ab[(r0 + 8) * AST + s * 8 + t4 * 2];
                af[mt][0] = p0.x; af[mt][1] = p1.x; af[mt][2] = p0.y; af[mt][3] = p1.y;
            }
#pragma unroll
            for (int nt = 0; nt < NTN; nt++) {
                const int cn = wn0 + nt * 8 + g8;
                uint2 bp = *(const uint2*)&Bb[(s * 4 + t4) * BNp * 2 + cn * 2];
#pragma unroll
                for (int mt = 0; mt < 2; mt++)
                    mma_tf32(acc[mt][nt][0], acc[mt][nt][1], acc[mt][nt][2], acc[mt][nt][3],
                             af[mt][0], af[mt][1], af[mt][2], af[mt][3], bp.x, bp.y);
            }
        }

        if (more) stsA(kt + 1, buf ^ 1, ra);
        __syncthreads();            // buf free for next cp.async; As[buf^1] stores done
        buf ^= 1;
    }

    // --- epilogue: + coef·bias, activation, store ---
#pragma unroll
    for (int mt = 0; mt < 2; mt++) {
#pragma unroll
        for (int half = 0; half < 2; half++) {
            const int rl = wm0 + mt * 16 + g8 + half * 8;
            float cfr[8];
#pragma unroll
            for (int e2 = 0; e2 < 8; e2++) cfr[e2] = coefS[rl * 9 + e2];
            float* orow = out + (size_t)(m0 + rl) * N + n0;
#pragma unroll
            for (int nt = 0; nt < NTN; nt++) {
                const int cl = wn0 + nt * 8 + t4 * 2;
                float v0 = acc[mt][nt][half * 2 + 0];
                float v1 = acc[mt][nt][half * 2 + 1];
#pragma unroll
                for (int e2 = 0; e2 < 8; e2++) {
                    v0 = fmaf(cfr[e2], biasS[e2 * BN + cl], v0);
                    v1 = fmaf(cfr[e2], biasS[e2 * BN + cl + 1], v1);
                }
                if (ELU) { v0 = elu1(v0); v1 = elu1(v1); }
                *(float2*)(orow + cl) = make_float2(v0, v1);
            }
        }
    }
}

// ---------------------------------------------------------------------------

static constexpr int smem_bytes(int BN) {
    return (2 * 128 * 40 + 2 * 16 * (BN + 4) * 2 + 128 * 9 + 8 * BN) * 4;
}

extern "C" void kernel_launch(void* const* d_in, const int* in_sizes, int n_in,
                              void* d_out, int out_size)
{
    const float* z   = (const float*)d_in[0];
    const float* c   = (const float*)d_in[1];
    const float* w0  = (const float*)d_in[2];
    const float* b0  = (const float*)d_in[3];
    const float* w1  = (const float*)d_in[4];
    const float* b1  = (const float*)d_in[5];
    const float* w2  = (const float*)d_in[6];
    const float* b2  = (const float*)d_in[7];
    const float* gw1 = (const float*)d_in[8];
    const float* gb1 = (const float*)d_in[9];
    const float* gw2 = (const float*)d_in[10];
    const float* gb2 = (const float*)d_in[11];
    const float* gw3 = (const float*)d_in[12];
    const float* gb3 = (const float*)d_in[13];

    float *coef, *h0, *h1;
    uint32_t *wp0, *wp1, *wp2;
    cudaGetSymbolAddress((void**)&coef, g_coef);
    cudaGetSymbolAddress((void**)&h0, g_h0);
    cudaGetSymbolAddress((void**)&h1, g_h1);
    cudaGetSymbolAddress((void**)&wp0, g_wp0);
    cudaGetSymbolAddress((void**)&wp1, g_wp1);
    cudaGetSymbolAddress((void**)&wp2, g_wp2);

    cudaFuncSetAttribute(mixed_tc_kernel<512, 1024, 128, true>,
                         cudaFuncAttributeMaxDynamicSharedMemorySize, smem_bytes(128));
    cudaFuncSetAttribute(mixed_tc_kernel<1024, 1024, 128, true>,
                         cudaFuncAttributeMaxDynamicSharedMemorySize, smem_bytes(128));
    cudaFuncSetAttribute(mixed_tc_kernel<1024, 512, 64, false>,
                         cudaFuncAttributeMaxDynamicSharedMemorySize, smem_bytes(64));

    // pack weights to tf32 pair layout
    {
        int t0 = (4608 / 2) * 1024;
        int t1 = (8704 / 2) * 1024;
        int t2 = (8704 / 2) * 512;
        pack_kernel<<<(t0 + 255) / 256, 256>>>(w0, wp0, 1024, t0);
        pack_kernel<<<(t1 + 255) / 256, 256>>>(w1, wp1, 1024, t1);
        pack_kernel<<<(t2 + 255) / 256, 256>>>(w2, wp2, 512, t2);
    }

    gate_kernel<<<NB / 8, 128>>>(z, c, gw1, gb1, gw2, gb2, gw3, gb3, coef);

    // layer0: M=4096, K=4608, N=1024
    mixed_tc_kernel<512, 1024, 128, true>
        <<<dim3(1024 / 128, NB / 128), 256, smem_bytes(128)>>>(z, c, wp0, b0, coef, h0);

    // layer1: M=4096, K=8704, N=1024
    mixed_tc_kernel<1024, 1024, 128, true>
        <<<dim3(1024 / 128, NB / 128), 256, smem_bytes(128)>>>(z, h0, wp1, b1, coef, h1);

    // layer2: M=4096, K=8704, N=512
    mixed_tc_kernel<1024, 512, 64, false>
        <<<dim3(512 / 64, NB / 128), 256, smem_bytes(64)>>>(z, h1, wp2, b2, coef, (float*)d_out);
}

// round 5
// speedup vs baseline: 1.3430x; 1.2922x over previous
#include <cuda_runtime.h>
#include <math.h>
#include <stdint.h>

#define NB 4096

// Scratch (device globals -- no allocation allowed)
__device__ float g_coef[NB * 8];
__device__ float g_h0[NB * 1024];
__device__ float g_h1[NB * 1024];
// tf32-packed, fragment-paired weights: [K/32][16][N] x uint2 {tf32(k), tf32(k+4)}
__device__ uint32_t g_wp0[(4608 / 2) * 1024 * 2];
__device__ uint32_t g_wp1[(8704 / 2) * 1024 * 2];
__device__ uint32_t g_wp2[(8704 / 2) * 512 * 2];

__device__ __forceinline__ float elu1(float x) {
    return x > 0.f ? x : expm1f(x);
}

__device__ __forceinline__ uint32_t f2tf(float x) {
    uint32_t r;
    asm("cvt.rna.tf32.f32 %0, %1;" : "=r"(r) : "f"(x));
    return r;
}

__device__ __forceinline__ void cp16(uint32_t smem_addr, const void* gptr) {
    asm volatile("cp.async.cg.shared.global [%0], [%1], 16;\n"
                 :: "r"(smem_addr), "l"(gptr));
}
__device__ __forceinline__ void cp_commit() {
    asm volatile("cp.async.commit_group;\n" ::);
}
__device__ __forceinline__ void cp_wait1() {
    asm volatile("cp.async.wait_group 1;\n" ::);
}

__device__ __forceinline__ void mma_tf32(float& d0, float& d1, float& d2, float& d3,
                                         uint32_t a0, uint32_t a1, uint32_t a2, uint32_t a3,
                                         uint32_t b0, uint32_t b1) {
    asm volatile(
        "mma.sync.aligned.m16n8k8.row.col.f32.tf32.tf32.f32 "
        "{%0,%1,%2,%3}, {%4,%5,%6,%7}, {%8,%9}, {%0,%1,%2,%3};\n"
        : "+f"(d0), "+f"(d1), "+f"(d2), "+f"(d3)
        : "r"(a0), "r"(a1), "r"(a2), "r"(a3), "r"(b0), "r"(b1));
}

// ---------------------------------------------------------------------------
// Weight pack (N compile-time => no runtime div):
// W[k][n] -> Wp[(kt*16 + s*4 + t4)*N + n] = uint2{ tf32(W[kt*32+s*8+t4][n]),
//                                                  tf32(W[kt*32+s*8+t4+4][n]) }
// ---------------------------------------------------------------------------
template <int N>
__global__ __launch_bounds__(256) void pack_kernel(
    const float* __restrict__ W, uint32_t* __restrict__ Wp, int total)
{
    int idx = blockIdx.x * 256 + threadIdx.x;   // over (K/2)*N
    if (idx >= total) return;
    int n = idx % N;
    int r = idx / N;                // pair-row = kt*16 + kp
    int kt = r >> 4, kp = r & 15;
    int k1 = kt * 32 + (kp >> 2) * 8 + (kp & 3);
    uint2 v;
    v.x = f2tf(W[(size_t)k1 * N + n]);
    v.y = f2tf(W[(size_t)(k1 + 4) * N + n]);
    ((uint2*)Wp)[(size_t)r * N + n] = v;
}

// ---------------------------------------------------------------------------
// Gate MLP (R2 version, no unroll pragmas -- measured faster)
// ---------------------------------------------------------------------------
__global__ __launch_bounds__(128) void gate_kernel(
    const float* __restrict__ z, const float* __restrict__ c,
    const float* __restrict__ gw1, const float* __restrict__ gb1,
    const float* __restrict__ gw2, const float* __restrict__ gb2,
    const float* __restrict__ gw3, const float* __restrict__ gb3,
    float* __restrict__ coef)
{
    constexpr int R = 8;
    __shared__ float xs[R][576];
    __shared__ float h1s[R][128];
    __shared__ float h2s[R][128];
    __shared__ float lg[R][8];

    const int tid = threadIdx.x;
    const int b0 = blockIdx.x * R;

    for (int idx = tid; idx < R * 576; idx += 128) {
        int r = idx / 576;
        int i = idx - r * 576;
        xs[r][i] = (i < 64) ? z[(b0 + r) * 64 + i] : c[(b0 + r) * 512 + (i - 64)];
    }
    __syncthreads();

    float acc[R];
    {
        float bv = gb1[tid];
#pragma unroll
        for (int r = 0; r < R; r++) acc[r] = bv;
        for (int i = 0; i < 576; i++) {
            float w = gw1[i * 128 + tid];
#pragma unroll
            for (int r = 0; r < R; r++) acc[r] = fmaf(xs[r][i], w, acc[r]);
        }
#pragma unroll
        for (int r = 0; r < R; r++) h1s[r][tid] = elu1(acc[r]);
    }
    __syncthreads();

    {
        float bv = gb2[tid];
#pragma unroll
        for (int r = 0; r < R; r++) acc[r] = bv;
        for (int i = 0; i < 128; i++) {
            float w = gw2[i * 128 + tid];
#pragma unroll
            for (int r = 0; r < R; r++) acc[r] = fmaf(h1s[r][i], w, acc[r]);
        }
#pragma unroll
        for (int r = 0; r < R; r++) h2s[r][tid] = elu1(acc[r]);
    }
    __syncthreads();

    if (tid < 64) {
        int r = tid >> 3, e = tid & 7;
        float s = gb3[e];
        for (int i = 0; i < 128; i++) s = fmaf(h2s[r][i], gw3[i * 8 + e], s);
        lg[r][e] = s;
    }
    __syncthreads();

    if (tid < 64) {
        int r = tid >> 3, e = tid & 7;
        float mx = lg[r][0];
#pragma unroll
        for (int j = 1; j < 8; j++) mx = fmaxf(mx, lg[r][j]);
        float sum = 0.f;
#pragma unroll
        for (int j = 0; j < 8; j++) sum += expf(lg[r][j] - mx);
        coef[(b0 + r) * 8 + e] = expf(lg[r][e] - mx) / sum;
    }
}

// ---------------------------------------------------------------------------
// Mixed layer tf32 GEMM. R2 structure exactly (cp.async A raw + per-use
// cvt/coef-mul, wait_group-1 two-stage pipeline). ONLY delta vs R2:
// B comes from the pre-packed tf32 pair layout -> fragment = 1 LDS.64, 0 cvt.
// ---------------------------------------------------------------------------
template <int XC, int N, int BN, bool ELU>
__global__ __launch_bounds__(256, 2) void mixed_tc_kernel(
    const float* __restrict__ z,
    const float* __restrict__ xp,
    const uint32_t* __restrict__ Wp,
    const float* __restrict__ bias,
    const float* __restrict__ coef,
    float* __restrict__ out)
{
    constexpr int BM = 128;
    constexpr int BK = 32;
    constexpr int IN = 64 + XC;
    constexpr int K = 8 * IN;
    constexpr int NT = K / BK;
    constexpr int AST = BK + 4;     // A row stride (floats): scalar loads conflict-free
    constexpr int BNp = BN + 4;     // B pair-row stride; BNp%16==4 -> LDS.64 conflict-free
    constexpr int WN = BN / 2;
    constexpr int NTN = WN / 8;

    extern __shared__ char smraw[];
    float* As = (float*)smraw;                       // 2 * BM * AST floats
    uint32_t* Bp = (uint32_t*)(As + 2 * BM * AST);   // 2 * 16 * BNp * 2 u32
    float* coefS = (float*)(Bp + 2 * 16 * BNp * 2);  // BM * 9
    float* biasS = coefS + BM * 9;                   // 8 * BN

    const int tid = threadIdx.x;
    const int m0 = blockIdx.y * BM;
    const int n0 = blockIdx.x * BN;
    const int w = tid >> 5, lane = tid & 31;
    const int wm0 = (w & 3) * 32;
    const int wn0 = (w >> 2) * WN;
    const int g8 = lane >> 2;
    const int t4 = lane & 3;

    // --- A staging: cp.async raw floats, layout As[m][k] stride AST ---
    auto loadA = [&](int kt, int stg) {
        const int e = (kt * BK) / IN;
        const int i0 = kt * BK - e * IN;
        float* dst = As + stg * BM * AST;
        const float* base;
        int stride;
        if (i0 < 64) { base = z + (size_t)m0 * 64 + i0; stride = 64; }
        else         { base = xp + (size_t)m0 * XC + (i0 - 64); stride = XC; }
#pragma unroll
        for (int j = 0; j < 4; j++) {
            int idx = j * 256 + tid;
            int row = idx >> 3;
            int kc4 = (idx & 7) * 4;
            uint32_t sa = (uint32_t)__cvta_generic_to_shared(dst + row * AST + kc4);
            cp16(sa, base + (size_t)row * stride + kc4);
        }
    };

    // --- B staging: cp.async of pre-converted tf32 pairs ---
    auto cpB = [&](int kt, int stg) {
        uint32_t dbase = (uint32_t)__cvta_generic_to_shared(Bp + stg * 16 * BNp * 2);
        const uint32_t* src = Wp + (size_t)kt * 16 * N * 2 + n0 * 2;
        constexpr int CH = 16 * (BN / 2) / 256;   // 16B chunks per thread
#pragma unroll
        for (int j = 0; j < CH; j++) {
            int idx = j * 256 + tid;
            int r = idx / (BN / 2);
            int c16 = idx - r * (BN / 2);
            cp16(dbase + (r * BNp * 2 + c16 * 4) * 4, src + (size_t)r * N * 2 + c16 * 4);
        }
    };

    // --- prologue ---
    loadA(0, 0);
    cpB(0, 0);
    cp_commit();

    for (int idx = tid; idx < BM * 8; idx += 256)
        coefS[(idx >> 3) * 9 + (idx & 7)] = coef[(size_t)(m0 + (idx >> 3)) * 8 + (idx & 7)];
    for (int idx = tid; idx < 8 * BN; idx += 256) {
        int e = idx / BN, cn = idx - e * BN;
        biasS[e * BN + cn] = bias[(size_t)e * N + n0 + cn];
    }

    float acc[2][NTN][4];
#pragma unroll
    for (int mt = 0; mt < 2; mt++)
#pragma unroll
        for (int nt = 0; nt < NTN; nt++)
#pragma unroll
            for (int q = 0; q < 4; q++) acc[mt][nt][q] = 0.f;

    int buf = 0;
    for (int kt = 0; kt < NT; kt++) {
        const bool more = (kt + 1 < NT);
        if (more) { loadA(kt + 1, buf ^ 1); cpB(kt + 1, buf ^ 1); }
        cp_commit();
        cp_wait1();
        __syncthreads();

        const int e = (kt * BK) / IN;
        float cf[4];
#pragma unroll
        for (int q = 0; q < 4; q++)
            cf[q] = coefS[(wm0 + g8 + q * 8) * 9 + e];

        const float* Ab = As + buf * BM * AST;
        const uint32_t* Bb = Bp + buf * 16 * BNp * 2;

#pragma unroll
        for (int s = 0; s < 4; s++) {
            uint32_t af[2][4];
#pragma unroll
            for (int mt = 0; mt < 2; mt++) {
                const int r0 = wm0 + mt * 16 + g8;
                af[mt][0] = f2tf(Ab[r0 * AST + s * 8 + t4] * cf[mt * 2 + 0]);
                af[mt][1] = f2tf(Ab[(r0 + 8) * AST + s * 8 + t4] * cf[mt * 2 + 1]);
                af[mt][2] = f2tf(Ab[r0 * AST + s * 8 + t4 + 4] * cf[mt * 2 + 0]);
                af[mt][3] = f2tf(Ab[(r0 + 8) * AST + s * 8 + t4 + 4] * cf[mt * 2 + 1]);
            }
#pragma unroll
            for (int nt = 0; nt < NTN; nt++) {
                const int cn = wn0 + nt * 8 + g8;
                uint2 bp = *(const uint2*)&Bb[(s * 4 + t4) * BNp * 2 + cn * 2];
#pragma unroll
                for (int mt = 0; mt < 2; mt++)
                    mma_tf32(acc[mt][nt][0], acc[mt][nt][1], acc[mt][nt][2], acc[mt][nt][3],
                             af[mt][0], af[mt][1], af[mt][2], af[mt][3], bp.x, bp.y);
            }
        }
        __syncthreads();
        buf ^= 1;
    }

    // --- epilogue: + coef·bias, activation, store ---
#pragma unroll
    for (int mt = 0; mt < 2; mt++) {
#pragma unroll
        for (int half = 0; half < 2; half++) {
            const int rl = wm0 + mt * 16 + g8 + half * 8;
            float cfr[8];
#pragma unroll
            for (int e2 = 0; e2 < 8; e2++) cfr[e2] = coefS[rl * 9 + e2];
            float* orow = out + (size_t)(m0 + rl) * N + n0;
#pragma unroll
            for (int nt = 0; nt < NTN; nt++) {
                const int cl = wn0 + nt * 8 + t4 * 2;
                float v0 = acc[mt][nt][half * 2 + 0];
                float v1 = acc[mt][nt][half * 2 + 1];
#pragma unroll
                for (int e2 = 0; e2 < 8; e2++) {
                    v0 = fmaf(cfr[e2], biasS[e2 * BN + cl], v0);
                    v1 = fmaf(cfr[e2], biasS[e2 * BN + cl + 1], v1);
                }
                if (ELU) { v0 = elu1(v0); v1 = elu1(v1); }
                *(float2*)(orow + cl) = make_float2(v0, v1);
            }
        }
    }
}

// ---------------------------------------------------------------------------

static constexpr int smem_bytes(int BN) {
    return (2 * 128 * 36 + 2 * 16 * (BN + 4) * 2 + 128 * 9 + 8 * BN) * 4;
}

extern "C" void kernel_launch(void* const* d_in, const int* in_sizes, int n_in,
                              void* d_out, int out_size)
{
    const float* z   = (const float*)d_in[0];
    const float* c   = (const float*)d_in[1];
    const float* w0  = (const float*)d_in[2];
    const float* b0  = (const float*)d_in[3];
    const float* w1  = (const float*)d_in[4];
    const float* b1  = (const float*)d_in[5];
    const float* w2  = (const float*)d_in[6];
    const float* b2  = (const float*)d_in[7];
    const float* gw1 = (const float*)d_in[8];
    const float* gb1 = (const float*)d_in[9];
    const float* gw2 = (const float*)d_in[10];
    const float* gb2 = (const float*)d_in[11];
    const float* gw3 = (const float*)d_in[12];
    const float* gb3 = (const float*)d_in[13];

    float *coef, *h0, *h1;
    uint32_t *wp0, *wp1, *wp2;
    cudaGetSymbolAddress((void**)&coef, g_coef);
    cudaGetSymbolAddress((void**)&h0, g_h0);
    cudaGetSymbolAddress((void**)&h1, g_h1);
    cudaGetSymbolAddress((void**)&wp0, g_wp0);
    cudaGetSymbolAddress((void**)&wp1, g_wp1);
    cudaGetSymbolAddress((void**)&wp2, g_wp2);

    cudaFuncSetAttribute(mixed_tc_kernel<512, 1024, 128, true>,
                         cudaFuncAttributeMaxDynamicSharedMemorySize, smem_bytes(128));
    cudaFuncSetAttribute(mixed_tc_kernel<1024, 1024, 128, true>,
                         cudaFuncAttributeMaxDynamicSharedMemorySize, smem_bytes(128));
    cudaFuncSetAttribute(mixed_tc_kernel<1024, 512, 64, false>,
                         cudaFuncAttributeMaxDynamicSharedMemorySize, smem_bytes(64));

    // pack weights to tf32 pair layout
    {
        int t0 = (4608 / 2) * 1024;
        int t1 = (8704 / 2) * 1024;
        int t2 = (8704 / 2) * 512;
        pack_kernel<1024><<<(t0 + 255) / 256, 256>>>(w0, wp0, t0);
        pack_kernel<1024><<<(t1 + 255) / 256, 256>>>(w1, wp1, t1);
        pack_kernel<512><<<(t2 + 255) / 256, 256>>>(w2, wp2, t2);
    }

    gate_kernel<<<NB / 8, 128>>>(z, c, gw1, gb1, gw2, gb2, gw3, gb3, coef);

    // layer0: M=4096, K=4608, N=1024
    mixed_tc_kernel<512, 1024, 128, true>
        <<<dim3(1024 / 128, NB / 128), 256, smem_bytes(128)>>>(z, c, wp0, b0, coef, h0);

    // layer1: M=4096, K=8704, N=1024
    mixed_tc_kernel<1024, 1024, 128, true>
        <<<dim3(1024 / 128, NB / 128), 256, smem_bytes(128)>>>(z, h0, wp1, b1, coef, h1);

    // layer2: M=4096, K=8704, N=512
    mixed_tc_kernel<1024, 512, 64, false>
        <<<dim3(512 / 64, NB / 128), 256, smem_bytes(64)>>>(z, h1, wp2, b2, coef, (float*)d_out);
}